// round 3
// baseline (speedup 1.0000x reference)
#include <cuda_runtime.h>

#define NQ 4096
#define TPB 256

// In-place 4096-pt FWHT per row, scale 1/64 folded into the load.
// One CTA per row. Each thread owns 16 values.
// Stage map (butterflies at distinct strides commute):
//   strides 1..8    : intra-thread (contiguous 16-chunk)
//   strides 16..256 : warp shuffle-xor on lane bits 0..4
//   strides 512..2048: intra-thread after one padded-smem exchange
__global__ void __launch_bounds__(TPB) fwht4096_kernel(const float* __restrict__ x,
                                                       float* __restrict__ y) {
    __shared__ float sm[NQ + NQ / 32];  // pad: idx = e + (e>>5); both access
                                        // patterns are bank-conflict-free.
    const int t = threadIdx.x;
    const size_t base = (size_t)blockIdx.x * NQ;
    const float* xr = x + base;
    float* yr = y + base;
    const float scale = 0.015625f;  // HAD_SCALE / X_H_SCALE = 1/sqrt(4096)

    float v[16];

    // ---- Load: 16 contiguous elements [16t, 16t+16), 4x LDG.128 ----
    {
        const float4* p = reinterpret_cast<const float4*>(xr + 16 * t);
#pragma unroll
        for (int q = 0; q < 4; q++) {
            float4 f = p[q];
            v[4 * q + 0] = f.x * scale;
            v[4 * q + 1] = f.y * scale;
            v[4 * q + 2] = f.z * scale;
            v[4 * q + 3] = f.w * scale;
        }
    }

    // ---- Strides 1,2,4,8: intra-thread butterflies over low 4 bits ----
#pragma unroll
    for (int bs = 1; bs < 16; bs <<= 1) {
#pragma unroll
        for (int i = 0; i < 16; i++) {
            if ((i & bs) == 0) {
                float a = v[i], b = v[i + bs];
                v[i] = a + b;
                v[i + bs] = a - b;
            }
        }
    }

    // ---- Strides 16..256: shuffle-xor on lane bits 0..4 ----
    // Each thread keeps the value for its own element index:
    //   bit==0 lane computes a+b, bit==1 lane computes a-b = (-1)*v + other.
#pragma unroll
    for (int b = 0; b < 5; b++) {
        const int mask = 1 << b;
        const float sgn = (t & mask) ? -1.0f : 1.0f;
#pragma unroll
        for (int i = 0; i < 16; i++) {
            float other = __shfl_xor_sync(0xffffffffu, v[i], mask);
            v[i] = fmaf(sgn, v[i], other);
        }
    }

    // ---- Exchange via padded smem ----
    // Write: e = 16t + i  -> banks (16t + (t>>1)) % 32, bijective over a warp.
#pragma unroll
    for (int i = 0; i < 16; i++) {
        int e = 16 * t + i;
        sm[e + (e >> 5)] = v[i];
    }
    __syncthreads();
    // Read: e = 2t + s + 512j -> banks (2t + (t>>4)) % 32, bijective.
#pragma unroll
    for (int j = 0; j < 8; j++) {
#pragma unroll
        for (int s = 0; s < 2; s++) {
            int e = 2 * t + s + 512 * j;
            v[2 * j + s] = sm[e + (e >> 5)];
        }
    }

    // ---- Strides 512,1024,2048: intra-thread over j bits ----
#pragma unroll
    for (int bs = 1; bs < 8; bs <<= 1) {
#pragma unroll
        for (int j = 0; j < 8; j++) {
            if ((j & bs) == 0) {
#pragma unroll
                for (int s = 0; s < 2; s++) {
                    float a = v[2 * j + s], b = v[2 * (j + bs) + s];
                    v[2 * j + s] = a + b;
                    v[2 * (j + bs) + s] = a - b;
                }
            }
        }
    }

    // ---- Store: 8x STG.64, consecutive lanes -> consecutive float2 ----
#pragma unroll
    for (int j = 0; j < 8; j++) {
        float2 o;
        o.x = v[2 * j];
        o.y = v[2 * j + 1];
        reinterpret_cast<float2*>(yr + 512 * j)[t] = o;
    }
}

extern "C" void kernel_launch(void* const* d_in, const int* in_sizes, int n_in,
                              void* d_out, int out_size) {
    const float* x = (const float*)d_in[0];
    float* y = (float*)d_out;
    const int rows = in_sizes[0] / NQ;  // 8192 rows of 4096
    fwht4096_kernel<<<rows, TPB>>>(x, y);
}

// round 6
// speedup vs baseline: 1.8798x; 1.8798x over previous
#include <cuda_runtime.h>

#define NQ 4096
#define TPB 256

// 4096-pt FWHT, radix-16^3: three register butterfly phases (4 dims each)
// joined by two shared-memory exchanges. No warp shuffles.
//
// Swizzle: sidx(e) = e ^ ((e>>5 & 3)<<2) ^ ((e>>8 & 1)<<4)
// Verified conflict-free for all four smem access patterns:
//   write1: float4 at e=16t+4q   -> group bits (t0^t4, q^t[2:1]) distinct per 8-lane phase
//   read1/write2: e=256*hi+16*i+lo (stride 16) -> bit8(=h) XOR into bit4 splits halves
//   read2: e=256*r+t (stride 256) -> r0 XOR into bit4, lanes hit 32 distinct banks
__device__ __forceinline__ int sidx(int e) {
    return e ^ (((e >> 5) & 3) << 2) ^ (((e >> 8) & 1) << 4);
}

__device__ __forceinline__ void butterfly16(float v[16]) {
#pragma unroll
    for (int bs = 1; bs < 16; bs <<= 1) {
#pragma unroll
        for (int i = 0; i < 16; i++) {
            if ((i & bs) == 0) {
                float a = v[i], b = v[i + bs];
                v[i] = a + b;
                v[i + bs] = a - b;
            }
        }
    }
}

__global__ void __launch_bounds__(TPB) fwht4096_kernel(const float* __restrict__ x,
                                                       float* __restrict__ y) {
    __shared__ float sm[NQ];  // 16 KB; swizzle is a bijection on [0,4096)
    const int t = threadIdx.x;
    const size_t base = (size_t)blockIdx.x * NQ;
    const float scale = 0.015625f;  // 1/sqrt(4096)

    float v[16];

    // ---- Load 16 contiguous floats (4x LDG.128), fold in scale ----
    {
        const float4* p = reinterpret_cast<const float4*>(x + base + 16 * t);
#pragma unroll
        for (int q = 0; q < 4; q++) {
            float4 f = p[q];
            v[4 * q + 0] = f.x * scale;
            v[4 * q + 1] = f.y * scale;
            v[4 * q + 2] = f.z * scale;
            v[4 * q + 3] = f.w * scale;
        }
    }

    // ---- Phase 1: dims 0-3 (reg-index butterflies) ----
    butterfly16(v);

    // ---- Exchange 1 write: 4x STS.128 at e = 16t + 4q ----
#pragma unroll
    for (int q = 0; q < 4; q++) {
        int sb = sidx(16 * t + 4 * q);  // swizzle bits are constant across the float4
        *reinterpret_cast<float4*>(sm + sb) =
            make_float4(v[4 * q], v[4 * q + 1], v[4 * q + 2], v[4 * q + 3]);
    }
    __syncthreads();

    // ---- Exchange 1 read: thread owns (hi = dims 8-11, lo = dims 0-3),
    //      regs i = dims 4-7:  e = hi*256 + i*16 + lo ----
    const int hi = (t >> 4) << 8;
    const int lo = t & 15;
#pragma unroll
    for (int i = 0; i < 16; i++)
        v[i] = sm[sidx(hi + i * 16 + lo)];

    // ---- Phase 2: dims 4-7 ----
    butterfly16(v);

    // ---- Exchange 2 write: SAME addresses this thread just read -> in-place,
    //      no barrier needed between read1 and write2 ----
#pragma unroll
    for (int i = 0; i < 16; i++)
        sm[sidx(hi + i * 16 + lo)] = v[i];
    __syncthreads();

    // ---- Exchange 2 read: regs r = dims 8-11:  e = r*256 + t ----
#pragma unroll
    for (int r = 0; r < 16; r++)
        v[r] = sm[sidx(r * 256 + t)];

    // ---- Phase 3: dims 8-11 ----
    butterfly16(v);

    // ---- Store: 16x STG.32, each instruction covers 128B contiguous per warp ----
    float* yr = y + base;
#pragma unroll
    for (int r = 0; r < 16; r++)
        yr[r * 256 + t] = v[r];
}

extern "C" void kernel_launch(void* const* d_in, const int* in_sizes, int n_in,
                              void* d_out, int out_size) {
    const float* x = (const float*)d_in[0];
    float* y = (float*)d_out;
    const int rows = in_sizes[0] / NQ;  // 8192 rows
    fwht4096_kernel<<<rows, TPB>>>(x, y);
}